// round 15
// baseline (speedup 1.0000x reference)
#include <cuda_runtime.h>
#include <cuda_fp16.h>
#include <math.h>
#include <stdint.h>

#define KTAGS 64
#define DDIM  128
#define VWORDS 50000
#define NV   (VWORDS + 2)
#define BATCHN 2048
#define TLEN 256
#define BOS_TAG 63
#define EOS_TAG 62
#define TINYV 1e-45f
#define SCL   0.015625f   // 1/64 folded scaling

typedef unsigned long long u64;

// pack two fp32 -> bf16x2 (first arg = hi half)
__device__ __forceinline__ uint32_t cvt_bf16x2(float hi, float lo) {
    uint32_t r; asm("cvt.rn.bf16x2.f32 %0, %1, %2;" : "=r"(r) : "f"(hi), "f"(lo)); return r;
}
// pack two fp32 -> f16x2 (first arg = hi half)
__device__ __forceinline__ uint32_t cvt_f16x2(float hi, float lo) {
    uint32_t r; asm("cvt.rn.f16x2.f32 %0, %1, %2;" : "=r"(r) : "f"(hi), "f"(lo)); return r;
}
__device__ __forceinline__ uint32_t hadd2(uint32_t a, uint32_t b) {
    uint32_t d; asm("add.rn.f16x2 %0,%1,%2;" : "=r"(d) : "r"(a), "r"(b)); return d;
}
__device__ __forceinline__ uint32_t hmul2(uint32_t a, uint32_t b) {
    uint32_t d; asm("mul.rn.f16x2 %0,%1,%2;" : "=r"(d) : "r"(a), "r"(b)); return d;
}
__device__ __forceinline__ float2 h2f2(uint32_t v) {
    __half2 h = *reinterpret_cast<__half2*>(&v);
    return __half22float2(h);
}
// bf16 MMA, f32 accum (emit table)
__device__ __forceinline__ void mma16816(float& d0, float& d1, float& d2, float& d3,
        uint32_t a0, uint32_t a1, uint32_t a2, uint32_t a3,
        uint32_t b0, uint32_t b1) {
    asm("mma.sync.aligned.m16n8k16.row.col.f32.bf16.bf16.f32 "
        "{%0,%1,%2,%3}, {%4,%5,%6,%7}, {%8,%9}, {%0,%1,%2,%3};"
        : "+f"(d0), "+f"(d1), "+f"(d2), "+f"(d3)
        : "r"(a0), "r"(a1), "r"(a2), "r"(a3), "r"(b0), "r"(b1));
}
// f16 MMA, f16 accum (scan): D {c0=row g cols 2q/2q+1, c1=row g+8}
__device__ __forceinline__ void mma16816h(uint32_t& c0, uint32_t& c1,
        uint32_t a0, uint32_t a1, uint32_t a2, uint32_t a3,
        uint32_t b0, uint32_t b1) {
    asm("mma.sync.aligned.m16n8k16.row.col.f16.f16.f16.f16 "
        "{%0,%1}, {%2,%3,%4,%5}, {%6,%7}, {%0,%1};"
        : "+r"(c0), "+r"(c1)
        : "r"(a0), "r"(a1), "r"(a2), "r"(a3), "r"(b0), "r"(b1));
}

// Scratch (static device global; no dynamic allocation)
// emission table, word-major, f16x2 packed: [w][32] u32, word (2c,2c+1)
__device__ uint32_t g_Bt16[(size_t)NV * 32];

// ---------------------------------------------------------------------------
// Kernel 1: emission table via bf16 tensor cores, f16x2 output.
// ---------------------------------------------------------------------------
__global__ __launch_bounds__(256) void emit_table_kernel(
        const float* __restrict__ ThetaB, const float* __restrict__ E) {
    __shared__ __align__(16) uint2 sBf[8][8][32];   // [kc][nb][lane], 16 KB

    int tid  = threadIdx.x;
    int w    = tid >> 5;
    int lane = tid & 31;
    int g    = lane >> 2;
    int q    = lane & 3;

    for (int idx = tid; idx < 2048; idx += 256) {
        int kc = idx >> 8, nb = (idx >> 5) & 7, ln = idx & 31;
        int gg = ln >> 2, qq = ln & 3;
        int n  = 8 * nb + gg;
        int k0 = 16 * kc + 2 * qq;
        uint2 b;
        b.x = cvt_bf16x2(ThetaB[n * DDIM + k0 + 1], ThetaB[n * DDIM + k0]);
        b.y = cvt_bf16x2(ThetaB[n * DDIM + k0 + 9], ThetaB[n * DDIM + k0 + 8]);
        sBf[kc][nb][ln] = b;
    }
    __syncthreads();

    int w0 = (blockIdx.x * 8 + w) * 16;
    int r0 = w0 + g;     if (r0 >= NV) r0 = NV - 1;
    int r1 = w0 + g + 8; if (r1 >= NV) r1 = NV - 1;
    const float* e0p = E + (size_t)r0 * DDIM;
    const float* e1p = E + (size_t)r1 * DDIM;

    uint32_t Afr[8][4];
#pragma unroll
    for (int kc = 0; kc < 8; kc++) {
        int k0 = 16 * kc + 2 * q;
        float2 x0 = *(const float2*)(e0p + k0);
        float2 x1 = *(const float2*)(e1p + k0);
        float2 y0 = *(const float2*)(e0p + k0 + 8);
        float2 y1 = *(const float2*)(e1p + k0 + 8);
        Afr[kc][0] = cvt_bf16x2(x0.y, x0.x);
        Afr[kc][1] = cvt_bf16x2(x1.y, x1.x);
        Afr[kc][2] = cvt_bf16x2(y0.y, y0.x);
        Afr[kc][3] = cvt_bf16x2(y1.y, y1.x);
    }

    float acc[8][4];
#pragma unroll
    for (int nb = 0; nb < 8; nb++) {
        acc[nb][0] = 0.f; acc[nb][1] = 0.f; acc[nb][2] = 0.f; acc[nb][3] = 0.f;
#pragma unroll
        for (int kc = 0; kc < 8; kc++) {
            uint2 b = sBf[kc][nb][lane];
            mma16816(acc[nb][0], acc[nb][1], acc[nb][2], acc[nb][3],
                     Afr[kc][0], Afr[kc][1], Afr[kc][2], Afr[kc][3], b.x, b.y);
        }
    }

#pragma unroll
    for (int nb = 0; nb < 8; nb++) {
        int cidx = 4 * nb + q;
        float v0 = __expf(acc[nb][0]);
        float v1 = __expf(acc[nb][1]);
        float v2 = __expf(acc[nb][2]);
        float v3 = __expf(acc[nb][3]);
        if (nb == 7 && q == 3) { v0 = TINYV; v1 = TINYV; v2 = TINYV; v3 = TINYV; }
        if (w0 + g < NV)
            g_Bt16[(size_t)(w0 + g) * 32 + cidx]     = cvt_f16x2(v1, v0);
        if (w0 + g + 8 < NV)
            g_Bt16[(size_t)(w0 + g + 8) * 32 + cidx] = cvt_f16x2(v3, v2);
    }
}

// ---------------------------------------------------------------------------
// Kernel 2: forward scan — SINGLE WARP per problem, full f16, NO exchange.
// One warp owns all 16 sentences AND all 64 output tags: 32 MMAs/step as
// 16 independent depth-2 chains; D(f16x2 regs) IS next step's A fragment
// (no CVT, no STS/LDS, no barrier in the loop).
// lane: g = lane>>2 (sentence row, +8 for second), q = lane&3.
//   Af[kc] = {d[2kc][0], d[2kc][1], d[2kc+1][0], d[2kc+1][1]}
// ---------------------------------------------------------------------------
__global__ __launch_bounds__(32, 1) void crf_scan_kernel(
        const float* __restrict__ WA,
        const int* __restrict__ words, float* __restrict__ out) {
    __shared__ __align__(16) float sWA[KTAGS * KTAGS];   // 16 KB
    __shared__ int sWT[TLEN][16];                         // 16 KB

    int lane = threadIdx.x;
    int g    = lane >> 2;     // 0..7
    int q    = lane & 3;      // 0..3
    int s0   = blockIdx.x * 16;

    for (int idx = lane; idx < KTAGS * KTAGS / 4; idx += 32)
        ((float4*)sWA)[idx] = ((const float4*)WA)[idx];
    for (int idx = lane; idx < 16 * TLEN; idx += 32) {
        int s = idx >> 8, tt = idx & (TLEN - 1);
        sWT[tt][s] = words[(size_t)(s0 + s) * TLEN + tt];
    }
    __syncwarp();

    // B fragments (f16) for ALL 8 nb blocks: col n = 8nb+g, k0 = 16kc+2q
    uint32_t Bf[4][8][2];
#pragma unroll
    for (int nb = 0; nb < 8; nb++) {
        int n = 8 * nb + g;
        bool bos = (n == BOS_TAG);
#pragma unroll
        for (int kc = 0; kc < 4; kc++) {
            int k0 = 16 * kc + 2 * q;
            float v0 = bos ? 0.0f : __expf(sWA[(k0)     * KTAGS + n]) * SCL;
            float v1 = bos ? 0.0f : __expf(sWA[(k0 + 1) * KTAGS + n]) * SCL;
            float v8 = bos ? 0.0f : __expf(sWA[(k0 + 8) * KTAGS + n]) * SCL;
            float v9 = bos ? 0.0f : __expf(sWA[(k0 + 9) * KTAGS + n]) * SCL;
            Bf[kc][nb][0] = cvt_f16x2(v1, v0);
            Bf[kc][nb][1] = cvt_f16x2(v9, v8);
        }
    }

    // alpha_1[s][n] = A'[BOS][n] * emis(pos 1)[n]; d[nb] = {row g, row g+8}
    uint32_t d[8][2];
    {
        int w1g  = sWT[1][g];
        int w1g8 = sWT[1][8 + g];
#pragma unroll
        for (int nb = 0; nb < 8; nb++) {
            int n0 = 8 * nb + 2 * q;
            float rb0 = (n0     == BOS_TAG) ? 0.0f : __expf(sWA[BOS_TAG * KTAGS + n0])     * SCL;
            float rb1 = (n0 + 1 == BOS_TAG) ? 0.0f : __expf(sWA[BOS_TAG * KTAGS + n0 + 1]) * SCL;
            int cidx = 4 * nb + q;
            float2 eA = h2f2(g_Bt16[(size_t)w1g  * 32 + cidx]);
            float2 eB = h2f2(g_Bt16[(size_t)w1g8 * 32 + cidx]);
            d[nb][0] = cvt_f16x2(rb1 * eA.y, rb0 * eA.x);
            d[nb][1] = cvt_f16x2(rb1 * eB.y, rb0 * eB.x);
        }
    }

    // prefetch emissions for step t=2
    uint32_t eg[8][2];
    {
        int w2g  = sWT[2][g];
        int w2g8 = sWT[2][8 + g];
#pragma unroll
        for (int nb = 0; nb < 8; nb++) {
            int cidx = 4 * nb + q;
            eg[nb][0] = g_Bt16[(size_t)w2g  * 32 + cidx];
            eg[nb][1] = g_Bt16[(size_t)w2g8 * 32 + cidx];
        }
    }

    for (int t = 2; t <= TLEN - 2; ++t) {
        // A fragments = current d regs (zero-cost remap)
        uint32_t Af[4][4];
#pragma unroll
        for (int kc = 0; kc < 4; kc++) {
            Af[kc][0] = d[2 * kc][0];
            Af[kc][1] = d[2 * kc][1];
            Af[kc][2] = d[2 * kc + 1][0];
            Af[kc][3] = d[2 * kc + 1][1];
        }

        // 32 MMAs: per nb two independent depth-2 chains (kc01, kc23)
        uint32_t cA[8][2], cB[8][2];
#pragma unroll
        for (int nb = 0; nb < 8; nb++) {
            cA[nb][0] = 0u; cA[nb][1] = 0u;
            cB[nb][0] = 0u; cB[nb][1] = 0u;
            mma16816h(cA[nb][0], cA[nb][1],
                      Af[0][0], Af[0][1], Af[0][2], Af[0][3], Bf[0][nb][0], Bf[0][nb][1]);
            mma16816h(cB[nb][0], cB[nb][1],
                      Af[2][0], Af[2][1], Af[2][2], Af[2][3], Bf[2][nb][0], Bf[2][nb][1]);
            mma16816h(cA[nb][0], cA[nb][1],
                      Af[1][0], Af[1][1], Af[1][2], Af[1][3], Bf[1][nb][0], Bf[1][nb][1]);
            mma16816h(cB[nb][0], cB[nb][1],
                      Af[3][0], Af[3][1], Af[3][2], Af[3][3], Bf[3][nb][0], Bf[3][nb][1]);
        }

        // prefetch emissions for t+1 (t=254 reads pos 255: valid, unused)
        uint32_t ng[8][2];
        {
            int wn  = sWT[t + 1][g];
            int wn8 = sWT[t + 1][8 + g];
#pragma unroll
            for (int nb = 0; nb < 8; nb++) {
                int cidx = 4 * nb + q;
                ng[nb][0] = g_Bt16[(size_t)wn  * 32 + cidx];
                ng[nb][1] = g_Bt16[(size_t)wn8 * 32 + cidx];
            }
        }

        // fold + emission multiply (f16x2)
#pragma unroll
        for (int nb = 0; nb < 8; nb++) {
#pragma unroll
            for (int r = 0; r < 2; r++) {
                d[nb][r] = hmul2(hadd2(cA[nb][r], cB[nb][r]), eg[nb][r]);
                eg[nb][r] = ng[nb][r];
            }
        }
    }

    // final transition into EOS (fp32; EOS weights recomputed from sWA)
    {
        float zg = 0.0f, zg8 = 0.0f;
#pragma unroll
        for (int nb = 0; nb < 8; nb++) {
            int n0 = 8 * nb + 2 * q;
            float e0 = __expf(sWA[(n0)     * KTAGS + EOS_TAG]) * SCL;
            float e1 = __expf(sWA[(n0 + 1) * KTAGS + EOS_TAG]) * SCL;
            float2 f0 = h2f2(d[nb][0]);
            float2 f1 = h2f2(d[nb][1]);
            zg  += f0.x * e0 + f0.y * e1;
            zg8 += f1.x * e0 + f1.y * e1;
        }
        zg  += __shfl_xor_sync(0xffffffffu, zg, 1);
        zg  += __shfl_xor_sync(0xffffffffu, zg, 2);
        zg8 += __shfl_xor_sync(0xffffffffu, zg8, 1);
        zg8 += __shfl_xor_sync(0xffffffffu, zg8, 2);
        if (q == 0) {
            // + 255 * log(64) = 1530 * ln2 (fixed-scaling compensation)
            out[s0 + g]     = logf(zg)  + 1060.5151862567153f;
            out[s0 + 8 + g] = logf(zg8) + 1060.5151862567153f;
        }
    }
}

// ---------------------------------------------------------------------------
extern "C" void kernel_launch(void* const* d_in, const int* in_sizes, int n_in,
                              void* d_out, int out_size) {
    const int*   words  = nullptr;
    const float* ThetaB = nullptr;
    const float* WA     = nullptr;
    const float* E      = nullptr;
    for (int i = 0; i < n_in; i++) {
        switch (in_sizes[i]) {
            case BATCHN * TLEN:   words  = (const int*)d_in[i];   break;
            case KTAGS * DDIM:    ThetaB = (const float*)d_in[i]; break;
            case KTAGS * KTAGS:   WA     = (const float*)d_in[i]; break;
            case NV * DDIM:       E      = (const float*)d_in[i]; break;
        }
    }
    float* out = (float*)d_out;

    emit_table_kernel<<<(NV + 127) / 128, 256>>>(ThetaB, E);
    crf_scan_kernel<<<BATCHN / 16, 32>>>(WA, words, out);
}

// round 16
// speedup vs baseline: 1.1557x; 1.1557x over previous
#include <cuda_runtime.h>
#include <cuda_fp16.h>
#include <math.h>
#include <stdint.h>

#define KTAGS 64
#define DDIM  128
#define VWORDS 50000
#define NV   (VWORDS + 2)
#define BATCHN 2048
#define TLEN 256
#define BOS_TAG 63
#define EOS_TAG 62
#define TINYV 1e-45f
#define SCL   0.015625f   // 1/64 folded scaling

typedef unsigned long long u64;

// pack two fp32 -> bf16x2 (first arg = hi half)
__device__ __forceinline__ uint32_t cvt_bf16x2(float hi, float lo) {
    uint32_t r; asm("cvt.rn.bf16x2.f32 %0, %1, %2;" : "=r"(r) : "f"(hi), "f"(lo)); return r;
}
// pack two fp32 -> f16x2 (first arg = hi half)
__device__ __forceinline__ uint32_t cvt_f16x2(float hi, float lo) {
    uint32_t r; asm("cvt.rn.f16x2.f32 %0, %1, %2;" : "=r"(r) : "f"(hi), "f"(lo)); return r;
}
__device__ __forceinline__ uint32_t hadd2(uint32_t a, uint32_t b) {
    uint32_t d; asm("add.rn.f16x2 %0,%1,%2;" : "=r"(d) : "r"(a), "r"(b)); return d;
}
__device__ __forceinline__ uint32_t hmul2(uint32_t a, uint32_t b) {
    uint32_t d; asm("mul.rn.f16x2 %0,%1,%2;" : "=r"(d) : "r"(a), "r"(b)); return d;
}
__device__ __forceinline__ float2 h2f2(uint32_t v) {
    __half2 h = *reinterpret_cast<__half2*>(&v);
    return __half22float2(h);
}
// bf16 MMA, f32 accum (emit table)
__device__ __forceinline__ void mma16816(float& d0, float& d1, float& d2, float& d3,
        uint32_t a0, uint32_t a1, uint32_t a2, uint32_t a3,
        uint32_t b0, uint32_t b1) {
    asm("mma.sync.aligned.m16n8k16.row.col.f32.bf16.bf16.f32 "
        "{%0,%1,%2,%3}, {%4,%5,%6,%7}, {%8,%9}, {%0,%1,%2,%3};"
        : "+f"(d0), "+f"(d1), "+f"(d2), "+f"(d3)
        : "r"(a0), "r"(a1), "r"(a2), "r"(a3), "r"(b0), "r"(b1));
}
// f16 MMA, f16 accum (scan): D {c0=row g cols 2q/2q+1, c1=row g+8}
__device__ __forceinline__ void mma16816h(uint32_t& c0, uint32_t& c1,
        uint32_t a0, uint32_t a1, uint32_t a2, uint32_t a3,
        uint32_t b0, uint32_t b1) {
    asm("mma.sync.aligned.m16n8k16.row.col.f16.f16.f16.f16 "
        "{%0,%1}, {%2,%3,%4,%5}, {%6,%7}, {%0,%1};"
        : "+r"(c0), "+r"(c1)
        : "r"(a0), "r"(a1), "r"(a2), "r"(a3), "r"(b0), "r"(b1));
}

// Scratch (static device globals; no dynamic allocation)
__device__ uint32_t g_Bt16[(size_t)NV * 32];              // emission table f16x2
__device__ int2     g_wp[(size_t)(BATCHN / 16) * TLEN * 8]; // word pairs [cta][t][g]

// ---------------------------------------------------------------------------
// Kernel 1: emission table via bf16 tensor cores, f16x2 output.
// ---------------------------------------------------------------------------
__global__ __launch_bounds__(256) void emit_table_kernel(
        const float* __restrict__ ThetaB, const float* __restrict__ E) {
    __shared__ __align__(16) uint2 sBf[8][8][32];

    int tid  = threadIdx.x;
    int w    = tid >> 5;
    int lane = tid & 31;
    int g    = lane >> 2;
    int q    = lane & 3;

    for (int idx = tid; idx < 2048; idx += 256) {
        int kc = idx >> 8, nb = (idx >> 5) & 7, ln = idx & 31;
        int gg = ln >> 2, qq = ln & 3;
        int n  = 8 * nb + gg;
        int k0 = 16 * kc + 2 * qq;
        uint2 b;
        b.x = cvt_bf16x2(ThetaB[n * DDIM + k0 + 1], ThetaB[n * DDIM + k0]);
        b.y = cvt_bf16x2(ThetaB[n * DDIM + k0 + 9], ThetaB[n * DDIM + k0 + 8]);
        sBf[kc][nb][ln] = b;
    }
    __syncthreads();

    int w0 = (blockIdx.x * 8 + w) * 16;
    int r0 = w0 + g;     if (r0 >= NV) r0 = NV - 1;
    int r1 = w0 + g + 8; if (r1 >= NV) r1 = NV - 1;
    const float* e0p = E + (size_t)r0 * DDIM;
    const float* e1p = E + (size_t)r1 * DDIM;

    uint32_t Afr[8][4];
#pragma unroll
    for (int kc = 0; kc < 8; kc++) {
        int k0 = 16 * kc + 2 * q;
        float2 x0 = *(const float2*)(e0p + k0);
        float2 x1 = *(const float2*)(e1p + k0);
        float2 y0 = *(const float2*)(e0p + k0 + 8);
        float2 y1 = *(const float2*)(e1p + k0 + 8);
        Afr[kc][0] = cvt_bf16x2(x0.y, x0.x);
        Afr[kc][1] = cvt_bf16x2(x1.y, x1.x);
        Afr[kc][2] = cvt_bf16x2(y0.y, y0.x);
        Afr[kc][3] = cvt_bf16x2(y1.y, y1.x);
    }

    float acc[8][4];
#pragma unroll
    for (int nb = 0; nb < 8; nb++) {
        acc[nb][0] = 0.f; acc[nb][1] = 0.f; acc[nb][2] = 0.f; acc[nb][3] = 0.f;
#pragma unroll
        for (int kc = 0; kc < 8; kc++) {
            uint2 b = sBf[kc][nb][lane];
            mma16816(acc[nb][0], acc[nb][1], acc[nb][2], acc[nb][3],
                     Afr[kc][0], Afr[kc][1], Afr[kc][2], Afr[kc][3], b.x, b.y);
        }
    }

#pragma unroll
    for (int nb = 0; nb < 8; nb++) {
        int cidx = 4 * nb + q;
        float v0 = __expf(acc[nb][0]);
        float v1 = __expf(acc[nb][1]);
        float v2 = __expf(acc[nb][2]);
        float v3 = __expf(acc[nb][3]);
        if (nb == 7 && q == 3) { v0 = TINYV; v1 = TINYV; v2 = TINYV; v3 = TINYV; }
        if (w0 + g < NV)
            g_Bt16[(size_t)(w0 + g) * 32 + cidx]     = cvt_f16x2(v1, v0);
        if (w0 + g + 8 < NV)
            g_Bt16[(size_t)(w0 + g + 8) * 32 + cidx] = cvt_f16x2(v3, v2);
    }
}

// ---------------------------------------------------------------------------
// Kernel 1b: word-pair table. g_wp[b][t][g] = (words[16b+g][t], words[16b+8+g][t])
// ---------------------------------------------------------------------------
__global__ __launch_bounds__(256) void words_pair_kernel(const int* __restrict__ words) {
    int b = blockIdx.x;
    int s0 = b * 16;
    for (int idx = threadIdx.x; idx < TLEN * 8; idx += 256) {
        int t = idx >> 3, g = idx & 7;
        g_wp[((size_t)b * TLEN + t) * 8 + g] =
            make_int2(words[(size_t)(s0 + g) * TLEN + t],
                      words[(size_t)(s0 + 8 + g) * TLEN + t]);
    }
}

// ---------------------------------------------------------------------------
// Kernel 2: forward scan, 4-warp N-split, full f16 (R14 base) with the
// bar->LDS window filled: after bar.sync (DEFER_BLOCKING), issue word LDG
// (global pair table — no smem touch), the 2 own-kc MMAs (register-only),
// and the emission LDGs BEFORE the exchange LDS that triggers the block.
// Chains per j: cA = (kc=w, kc=w+1), cB = (kc=w+2, kc=w+3) mod 4.
// lane: g = lane>>2 (sentence row, +8 for second), q = lane&3.
// ---------------------------------------------------------------------------
__global__ __launch_bounds__(128, 1) void crf_scan_kernel(
        const float* __restrict__ WA, float* __restrict__ out) {
    __shared__ __align__(16) float sWA[KTAGS * KTAGS];   // 16 KB
    __shared__ __align__(16) uint4 sX[2][4][32];          // 4 KB exchange
    __shared__ float sZ[4][16];

    int tid  = threadIdx.x;
    int w    = tid >> 5;      // warp 0..3 = output-tag block
    int lane = tid & 31;
    int g    = lane >> 2;     // 0..7
    int q    = lane & 3;      // 0..3
    int s0   = blockIdx.x * 16;

    for (int idx = tid; idx < KTAGS * KTAGS / 4; idx += 128)
        ((float4*)sWA)[idx] = ((const float4*)WA)[idx];
    __syncthreads();

    // kc rotation for this warp (runtime indices, fragments stored rotated)
    int K0 = w, K1 = (w + 1) & 3, K2 = (w + 2) & 3, K3 = (w + 3) & 3;

    // B fragments (f16), stored ROTATED: BfO[o] = B for kc=(w+o)&3
    uint32_t BfO[4][2][2];
#pragma unroll
    for (int j = 0; j < 2; j++) {
        int n = 16 * w + 8 * j + g;
        bool bos = (n == BOS_TAG);
        int kcs[4] = {K0, K1, K2, K3};
#pragma unroll
        for (int o = 0; o < 4; o++) {
            int k0 = 16 * kcs[o] + 2 * q;
            float v0 = bos ? 0.0f : __expf(sWA[(k0)     * KTAGS + n]) * SCL;
            float v1 = bos ? 0.0f : __expf(sWA[(k0 + 1) * KTAGS + n]) * SCL;
            float v8 = bos ? 0.0f : __expf(sWA[(k0 + 8) * KTAGS + n]) * SCL;
            float v9 = bos ? 0.0f : __expf(sWA[(k0 + 9) * KTAGS + n]) * SCL;
            BfO[o][j][0] = cvt_f16x2(v1, v0);
            BfO[o][j][1] = cvt_f16x2(v9, v8);
        }
    }

    int cidx[2];
    cidx[0] = 8 * w + q;
    cidx[1] = 8 * w + 4 + q;

    const int2* wbase = g_wp + (size_t)blockIdx.x * TLEN * 8 + g;  // index: [t*8]

    // alpha_1[s][n] = A'[BOS][n] * emis(pos 1)[n]; d[j] = {row g, row g+8} f16x2
    uint32_t d[2][2];
    {
        int2 wp1 = wbase[1 * 8];
#pragma unroll
        for (int j = 0; j < 2; j++) {
            int n0 = 16 * w + 8 * j + 2 * q;
            float rb0 = (n0     == BOS_TAG) ? 0.0f : __expf(sWA[BOS_TAG * KTAGS + n0])     * SCL;
            float rb1 = (n0 + 1 == BOS_TAG) ? 0.0f : __expf(sWA[BOS_TAG * KTAGS + n0 + 1]) * SCL;
            float2 eA = h2f2(g_Bt16[(size_t)wp1.x * 32 + cidx[j]]);
            float2 eB = h2f2(g_Bt16[(size_t)wp1.y * 32 + cidx[j]]);
            d[j][0] = cvt_f16x2(rb1 * eA.y, rb0 * eA.x);
            d[j][1] = cvt_f16x2(rb1 * eB.y, rb0 * eB.x);
        }
    }

    // emissions for t=2; word pair for t=3
    uint32_t eg[2][2];
    {
        int2 wp2 = wbase[2 * 8];
#pragma unroll
        for (int j = 0; j < 2; j++) {
            eg[j][0] = g_Bt16[(size_t)wp2.x * 32 + cidx[j]];
            eg[j][1] = g_Bt16[(size_t)wp2.y * 32 + cidx[j]];
        }
    }
    int2 wpn = wbase[3 * 8];   // words for t=3

    int p = 0;
#pragma unroll 2
    for (int t = 2; t <= TLEN - 2; ++t) {
        // publish own Af[w] slice — d regs ARE the fragment
        uint4 my;
        my.x = d[0][0]; my.y = d[0][1]; my.z = d[1][0]; my.w = d[1][1];
        sX[p][w][lane] = my;
        __syncthreads();   // DEFER_BLOCKING: arrival posted, block deferred

        // ---- bar->LDS window: global loads + register-only MMAs ----
        int tn = t + 2; if (tn > TLEN - 1) tn = TLEN - 1;
        int2 wp2f = wbase[tn * 8];                    // words for t+2 (LDG.64)

        uint32_t cA[2][2], cB[2][2];
#pragma unroll
        for (int j = 0; j < 2; j++) {                 // own-kc MMAs (register-only)
            cA[j][0] = 0u; cA[j][1] = 0u;
            mma16816h(cA[j][0], cA[j][1],
                      my.x, my.y, my.z, my.w, BfO[0][j][0], BfO[0][j][1]);
        }

        uint32_t ng[2][2];                            // emissions t+1 (LDG, words in regs)
#pragma unroll
        for (int j = 0; j < 2; j++) {
            ng[j][0] = g_Bt16[(size_t)wpn.x * 32 + cidx[j]];
            ng[j][1] = g_Bt16[(size_t)wpn.y * 32 + cidx[j]];
        }

        // ---- exchange LDS (deferred block engages here) ----
        uint4 v1 = sX[p][K1][lane];
        uint4 v2 = sX[p][K2][lane];
        uint4 v3 = sX[p][K3][lane];

#pragma unroll
        for (int j = 0; j < 2; j++) {
            cB[j][0] = 0u; cB[j][1] = 0u;
            mma16816h(cB[j][0], cB[j][1],
                      v2.x, v2.y, v2.z, v2.w, BfO[2][j][0], BfO[2][j][1]);
            mma16816h(cA[j][0], cA[j][1],
                      v1.x, v1.y, v1.z, v1.w, BfO[1][j][0], BfO[1][j][1]);
            mma16816h(cB[j][0], cB[j][1],
                      v3.x, v3.y, v3.z, v3.w, BfO[3][j][0], BfO[3][j][1]);
        }

        // fold + emission multiply (f16x2)
#pragma unroll
        for (int j = 0; j < 2; j++) {
#pragma unroll
            for (int r = 0; r < 2; r++) {
                d[j][r] = hmul2(hadd2(cA[j][r], cB[j][r]), eg[j][r]);
                eg[j][r] = ng[j][r];
            }
        }
        wpn = wp2f;
        p ^= 1;
    }

    // final transition into EOS (fp32)
    {
        float zg = 0.0f, zg8 = 0.0f;
#pragma unroll
        for (int j = 0; j < 2; j++) {
            int n0 = 16 * w + 8 * j + 2 * q;
            float e0 = __expf(sWA[(n0)     * KTAGS + EOS_TAG]) * SCL;
            float e1 = __expf(sWA[(n0 + 1) * KTAGS + EOS_TAG]) * SCL;
            float2 f0 = h2f2(d[j][0]);
            float2 f1 = h2f2(d[j][1]);
            zg  += f0.x * e0 + f0.y * e1;
            zg8 += f1.x * e0 + f1.y * e1;
        }
        zg  += __shfl_xor_sync(0xffffffffu, zg, 1);
        zg  += __shfl_xor_sync(0xffffffffu, zg, 2);
        zg8 += __shfl_xor_sync(0xffffffffu, zg8, 1);
        zg8 += __shfl_xor_sync(0xffffffffu, zg8, 2);
        if (q == 0) {
            sZ[w][g]     = zg;
            sZ[w][8 + g] = zg8;
        }
    }
    __syncthreads();
    if (tid < 16) {
        float z = sZ[0][tid] + sZ[1][tid] + sZ[2][tid] + sZ[3][tid];
        // + 255 * log(64) = 1530 * ln2 (fixed-scaling compensation)
        out[s0 + tid] = logf(z) + 1060.5151862567153f;
    }
}

// ---------------------------------------------------------------------------
extern "C" void kernel_launch(void* const* d_in, const int* in_sizes, int n_in,
                              void* d_out, int out_size) {
    const int*   words  = nullptr;
    const float* ThetaB = nullptr;
    const float* WA     = nullptr;
    const float* E      = nullptr;
    for (int i = 0; i < n_in; i++) {
        switch (in_sizes[i]) {
            case BATCHN * TLEN:   words  = (const int*)d_in[i];   break;
            case KTAGS * DDIM:    ThetaB = (const float*)d_in[i]; break;
            case KTAGS * KTAGS:   WA     = (const float*)d_in[i]; break;
            case NV * DDIM:       E      = (const float*)d_in[i]; break;
        }
    }
    float* out = (float*)d_out;

    words_pair_kernel<<<BATCHN / 16, 256>>>(words);
    emit_table_kernel<<<(NV + 127) / 128, 256>>>(ThetaB, E);
    crf_scan_kernel<<<BATCHN / 16, 128>>>(WA, out);
}

// round 17
// speedup vs baseline: 1.1561x; 1.0004x over previous
#include <cuda_runtime.h>
#include <cuda_fp16.h>
#include <math.h>
#include <stdint.h>

#define KTAGS 64
#define DDIM  128
#define VWORDS 50000
#define NV   (VWORDS + 2)
#define BATCHN 2048
#define TLEN 256
#define BOS_TAG 63
#define EOS_TAG 62
#define TINYV 1e-45f
#define SCL   0.015625f   // 1/64 folded scaling

typedef unsigned long long u64;

// pack two fp32 -> bf16x2 (first arg = hi half)
__device__ __forceinline__ uint32_t cvt_bf16x2(float hi, float lo) {
    uint32_t r; asm("cvt.rn.bf16x2.f32 %0, %1, %2;" : "=r"(r) : "f"(hi), "f"(lo)); return r;
}
// pack two fp32 -> f16x2 (first arg = hi half)
__device__ __forceinline__ uint32_t cvt_f16x2(float hi, float lo) {
    uint32_t r; asm("cvt.rn.f16x2.f32 %0, %1, %2;" : "=r"(r) : "f"(hi), "f"(lo)); return r;
}
__device__ __forceinline__ uint32_t hadd2(uint32_t a, uint32_t b) {
    uint32_t d; asm("add.rn.f16x2 %0,%1,%2;" : "=r"(d) : "r"(a), "r"(b)); return d;
}
__device__ __forceinline__ uint32_t hmul2(uint32_t a, uint32_t b) {
    uint32_t d; asm("mul.rn.f16x2 %0,%1,%2;" : "=r"(d) : "r"(a), "r"(b)); return d;
}
__device__ __forceinline__ float2 h2f2(uint32_t v) {
    __half2 h = *reinterpret_cast<__half2*>(&v);
    return __half22float2(h);
}
// bf16 MMA, f32 accum (emit table)
__device__ __forceinline__ void mma16816(float& d0, float& d1, float& d2, float& d3,
        uint32_t a0, uint32_t a1, uint32_t a2, uint32_t a3,
        uint32_t b0, uint32_t b1) {
    asm("mma.sync.aligned.m16n8k16.row.col.f32.bf16.bf16.f32 "
        "{%0,%1,%2,%3}, {%4,%5,%6,%7}, {%8,%9}, {%0,%1,%2,%3};"
        : "+f"(d0), "+f"(d1), "+f"(d2), "+f"(d3)
        : "r"(a0), "r"(a1), "r"(a2), "r"(a3), "r"(b0), "r"(b1));
}
// f16 MMA, f16 accum (scan): D {c0=row g cols 2q/2q+1, c1=row g+8}
__device__ __forceinline__ void mma16816h(uint32_t& c0, uint32_t& c1,
        uint32_t a0, uint32_t a1, uint32_t a2, uint32_t a3,
        uint32_t b0, uint32_t b1) {
    asm("mma.sync.aligned.m16n8k16.row.col.f16.f16.f16.f16 "
        "{%0,%1}, {%2,%3,%4,%5}, {%6,%7}, {%0,%1};"
        : "+r"(c0), "+r"(c1)
        : "r"(a0), "r"(a1), "r"(a2), "r"(a3), "r"(b0), "r"(b1));
}

// Scratch (static device global; no dynamic allocation)
__device__ uint32_t g_Bt16[(size_t)NV * 32];   // emission table f16x2

// ---------------------------------------------------------------------------
// Kernel 1: emission table via bf16 tensor cores, f16x2 output.
// ---------------------------------------------------------------------------
__global__ __launch_bounds__(256) void emit_table_kernel(
        const float* __restrict__ ThetaB, const float* __restrict__ E) {
    __shared__ __align__(16) uint2 sBf[8][8][32];

    int tid  = threadIdx.x;
    int w    = tid >> 5;
    int lane = tid & 31;
    int g    = lane >> 2;
    int q    = lane & 3;

    for (int idx = tid; idx < 2048; idx += 256) {
        int kc = idx >> 8, nb = (idx >> 5) & 7, ln = idx & 31;
        int gg = ln >> 2, qq = ln & 3;
        int n  = 8 * nb + gg;
        int k0 = 16 * kc + 2 * qq;
        uint2 b;
        b.x = cvt_bf16x2(ThetaB[n * DDIM + k0 + 1], ThetaB[n * DDIM + k0]);
        b.y = cvt_bf16x2(ThetaB[n * DDIM + k0 + 9], ThetaB[n * DDIM + k0 + 8]);
        sBf[kc][nb][ln] = b;
    }
    __syncthreads();

    int w0 = (blockIdx.x * 8 + w) * 16;
    int r0 = w0 + g;     if (r0 >= NV) r0 = NV - 1;
    int r1 = w0 + g + 8; if (r1 >= NV) r1 = NV - 1;
    const float* e0p = E + (size_t)r0 * DDIM;
    const float* e1p = E + (size_t)r1 * DDIM;

    uint32_t Afr[8][4];
#pragma unroll
    for (int kc = 0; kc < 8; kc++) {
        int k0 = 16 * kc + 2 * q;
        float2 x0 = *(const float2*)(e0p + k0);
        float2 x1 = *(const float2*)(e1p + k0);
        float2 y0 = *(const float2*)(e0p + k0 + 8);
        float2 y1 = *(const float2*)(e1p + k0 + 8);
        Afr[kc][0] = cvt_bf16x2(x0.y, x0.x);
        Afr[kc][1] = cvt_bf16x2(x1.y, x1.x);
        Afr[kc][2] = cvt_bf16x2(y0.y, y0.x);
        Afr[kc][3] = cvt_bf16x2(y1.y, y1.x);
    }

    float acc[8][4];
#pragma unroll
    for (int nb = 0; nb < 8; nb++) {
        acc[nb][0] = 0.f; acc[nb][1] = 0.f; acc[nb][2] = 0.f; acc[nb][3] = 0.f;
#pragma unroll
        for (int kc = 0; kc < 8; kc++) {
            uint2 b = sBf[kc][nb][lane];
            mma16816(acc[nb][0], acc[nb][1], acc[nb][2], acc[nb][3],
                     Afr[kc][0], Afr[kc][1], Afr[kc][2], Afr[kc][3], b.x, b.y);
        }
    }

#pragma unroll
    for (int nb = 0; nb < 8; nb++) {
        int cidx = 4 * nb + q;
        float v0 = __expf(acc[nb][0]);
        float v1 = __expf(acc[nb][1]);
        float v2 = __expf(acc[nb][2]);
        float v3 = __expf(acc[nb][3]);
        if (nb == 7 && q == 3) { v0 = TINYV; v1 = TINYV; v2 = TINYV; v3 = TINYV; }
        if (w0 + g < NV)
            g_Bt16[(size_t)(w0 + g) * 32 + cidx]     = cvt_f16x2(v1, v0);
        if (w0 + g + 8 < NV)
            g_Bt16[(size_t)(w0 + g + 8) * 32 + cidx] = cvt_f16x2(v3, v2);
    }
}

// ---------------------------------------------------------------------------
// Kernel 2: forward scan, 4-warp N-split, full f16, bar->LDS window filled.
// Words are loaded DIRECTLY from the original words tensor (two LDG.32 per
// (g,row) pair; 16 KB working set per CTA -> L1-resident), so the prefetch
// issues in the post-barrier window without touching smem (DEFER_BLOCKING).
// Chains per j: cA = (kc=w -> w+1), cB = (kc=w+2 -> w+3) mod 4.
// lane: g = lane>>2 (sentence row, +8 for second), q = lane&3.
// ---------------------------------------------------------------------------
__global__ __launch_bounds__(128, 1) void crf_scan_kernel(
        const float* __restrict__ WA,
        const int* __restrict__ words, float* __restrict__ out) {
    __shared__ __align__(16) float sWA[KTAGS * KTAGS];   // 16 KB
    __shared__ __align__(16) uint4 sX[2][4][32];          // 4 KB exchange
    __shared__ float sZ[4][16];

    int tid  = threadIdx.x;
    int w    = tid >> 5;      // warp 0..3 = output-tag block
    int lane = tid & 31;
    int g    = lane >> 2;     // 0..7
    int q    = lane & 3;      // 0..3
    int s0   = blockIdx.x * 16;

    for (int idx = tid; idx < KTAGS * KTAGS / 4; idx += 128)
        ((float4*)sWA)[idx] = ((const float4*)WA)[idx];
    __syncthreads();

    // kc rotation for this warp (fragments stored rotated)
    int K1 = (w + 1) & 3, K2 = (w + 2) & 3, K3 = (w + 3) & 3;

    // B fragments (f16), stored ROTATED: BfO[o] = B for kc=(w+o)&3
    uint32_t BfO[4][2][2];
#pragma unroll
    for (int j = 0; j < 2; j++) {
        int n = 16 * w + 8 * j + g;
        bool bos = (n == BOS_TAG);
        int kcs[4] = {w, K1, K2, K3};
#pragma unroll
        for (int o = 0; o < 4; o++) {
            int k0 = 16 * kcs[o] + 2 * q;
            float v0 = bos ? 0.0f : __expf(sWA[(k0)     * KTAGS + n]) * SCL;
            float v1 = bos ? 0.0f : __expf(sWA[(k0 + 1) * KTAGS + n]) * SCL;
            float v8 = bos ? 0.0f : __expf(sWA[(k0 + 8) * KTAGS + n]) * SCL;
            float v9 = bos ? 0.0f : __expf(sWA[(k0 + 9) * KTAGS + n]) * SCL;
            BfO[o][j][0] = cvt_f16x2(v1, v0);
            BfO[o][j][1] = cvt_f16x2(v9, v8);
        }
    }

    int cidx[2];
    cidx[0] = 8 * w + q;
    cidx[1] = 8 * w + 4 + q;

    // direct word-row pointers (L1-resident after first sweep)
    const int* wr0 = words + (size_t)(s0 + g)     * TLEN;
    const int* wr8 = words + (size_t)(s0 + 8 + g) * TLEN;

    // alpha_1[s][n] = A'[BOS][n] * emis(pos 1)[n]; d[j] = {row g, row g+8} f16x2
    uint32_t d[2][2];
    {
        int wa = wr0[1], wb = wr8[1];
#pragma unroll
        for (int j = 0; j < 2; j++) {
            int n0 = 16 * w + 8 * j + 2 * q;
            float rb0 = (n0     == BOS_TAG) ? 0.0f : __expf(sWA[BOS_TAG * KTAGS + n0])     * SCL;
            float rb1 = (n0 + 1 == BOS_TAG) ? 0.0f : __expf(sWA[BOS_TAG * KTAGS + n0 + 1]) * SCL;
            float2 eA = h2f2(g_Bt16[(size_t)wa * 32 + cidx[j]]);
            float2 eB = h2f2(g_Bt16[(size_t)wb * 32 + cidx[j]]);
            d[j][0] = cvt_f16x2(rb1 * eA.y, rb0 * eA.x);
            d[j][1] = cvt_f16x2(rb1 * eB.y, rb0 * eB.x);
        }
    }

    // emissions for t=2; word pair for t=3
    uint32_t eg[2][2];
    {
        int wa = wr0[2], wb = wr8[2];
#pragma unroll
        for (int j = 0; j < 2; j++) {
            eg[j][0] = g_Bt16[(size_t)wa * 32 + cidx[j]];
            eg[j][1] = g_Bt16[(size_t)wb * 32 + cidx[j]];
        }
    }
    int wna = wr0[3], wnb = wr8[3];   // words for t=3

    int p = 0;
#pragma unroll 2
    for (int t = 2; t <= TLEN - 2; ++t) {
        // publish own Af[w] slice — d regs ARE the fragment
        uint4 my;
        my.x = d[0][0]; my.y = d[0][1]; my.z = d[1][0]; my.w = d[1][1];
        sX[p][w][lane] = my;
        __syncthreads();   // DEFER_BLOCKING: arrival posted, block deferred

        // ---- bar->LDS window: global loads + register-only MMAs ----
        int tn = t + 2; if (tn > TLEN - 1) tn = TLEN - 1;
        int w2a = wr0[tn], w2b = wr8[tn];             // words for t+2 (LDG.32 x2)

        uint32_t cA[2][2], cB[2][2];
#pragma unroll
        for (int j = 0; j < 2; j++) {                 // own-kc MMAs (register-only)
            cA[j][0] = 0u; cA[j][1] = 0u;
            mma16816h(cA[j][0], cA[j][1],
                      my.x, my.y, my.z, my.w, BfO[0][j][0], BfO[0][j][1]);
        }

        uint32_t ng[2][2];                            // emissions t+1 (words in regs)
#pragma unroll
        for (int j = 0; j < 2; j++) {
            ng[j][0] = g_Bt16[(size_t)wna * 32 + cidx[j]];
            ng[j][1] = g_Bt16[(size_t)wnb * 32 + cidx[j]];
        }

        // ---- exchange LDS (deferred block engages here) ----
        uint4 v1 = sX[p][K1][lane];
        uint4 v2 = sX[p][K2][lane];
        uint4 v3 = sX[p][K3][lane];

#pragma unroll
        for (int j = 0; j < 2; j++) {
            cB[j][0] = 0u; cB[j][1] = 0u;
            mma16816h(cB[j][0], cB[j][1],
                      v2.x, v2.y, v2.z, v2.w, BfO[2][j][0], BfO[2][j][1]);
            mma16816h(cA[j][0], cA[j][1],
                      v1.x, v1.y, v1.z, v1.w, BfO[1][j][0], BfO[1][j][1]);
            mma16816h(cB[j][0], cB[j][1],
                      v3.x, v3.y, v3.z, v3.w, BfO[3][j][0], BfO[3][j][1]);
        }

        // fold + emission multiply (f16x2)
#pragma unroll
        for (int j = 0; j < 2; j++) {
#pragma unroll
            for (int r = 0; r < 2; r++) {
                d[j][r] = hmul2(hadd2(cA[j][r], cB[j][r]), eg[j][r]);
                eg[j][r] = ng[j][r];
            }
        }
        wna = w2a; wnb = w2b;
        p ^= 1;
    }

    // final transition into EOS (fp32)
    {
        float zg = 0.0f, zg8 = 0.0f;
#pragma unroll
        for (int j = 0; j < 2; j++) {
            int n0 = 16 * w + 8 * j + 2 * q;
            float e0 = __expf(sWA[(n0)     * KTAGS + EOS_TAG]) * SCL;
            float e1 = __expf(sWA[(n0 + 1) * KTAGS + EOS_TAG]) * SCL;
            float2 f0 = h2f2(d[j][0]);
            float2 f1 = h2f2(d[j][1]);
            zg  += f0.x * e0 + f0.y * e1;
            zg8 += f1.x * e0 + f1.y * e1;
        }
        zg  += __shfl_xor_sync(0xffffffffu, zg, 1);
        zg  += __shfl_xor_sync(0xffffffffu, zg, 2);
        zg8 += __shfl_xor_sync(0xffffffffu, zg8, 1);
        zg8 += __shfl_xor_sync(0xffffffffu, zg8, 2);
        if (q == 0) {
            sZ[w][g]     = zg;
            sZ[w][8 + g] = zg8;
        }
    }
    __syncthreads();
    if (tid < 16) {
        float z = sZ[0][tid] + sZ[1][tid] + sZ[2][tid] + sZ[3][tid];
        // + 255 * log(64) = 1530 * ln2 (fixed-scaling compensation)
        out[s0 + tid] = logf(z) + 1060.5151862567153f;
    }
}

// ---------------------------------------------------------------------------
extern "C" void kernel_launch(void* const* d_in, const int* in_sizes, int n_in,
                              void* d_out, int out_size) {
    const int*   words  = nullptr;
    const float* ThetaB = nullptr;
    const float* WA     = nullptr;
    const float* E      = nullptr;
    for (int i = 0; i < n_in; i++) {
        switch (in_sizes[i]) {
            case BATCHN * TLEN:   words  = (const int*)d_in[i];   break;
            case KTAGS * DDIM:    ThetaB = (const float*)d_in[i]; break;
            case KTAGS * KTAGS:   WA     = (const float*)d_in[i]; break;
            case NV * DDIM:       E      = (const float*)d_in[i]; break;
        }
    }
    float* out = (float*)d_out;

    emit_table_kernel<<<(NV + 127) / 128, 256>>>(ThetaB, E);
    crf_scan_kernel<<<BATCHN / 16, 128>>>(WA, words, out);
}